// round 7
// baseline (speedup 1.0000x reference)
#include <cuda_runtime.h>
#include <cuda_bf16.h>
#include <math.h>
#include <stdint.h>

#define TT    19
#define INLEN 10
#define GPX   8192
#define LS    (GPX*64)
typedef __nv_bfloat16 bf;

// ---------------- device scratch ----------------
__device__ __align__(16) bf g_xh[INLEN*LS], g_xl[INLEN*LS];
__device__ __align__(16) bf g_hh[4*LS],     g_hl[4*LS];
__device__ __align__(16) bf g_mh[LS],       g_ml[LS];
__device__ __align__(16) bf g_memh[GPX*128], g_meml[GPX*128];
__device__ __align__(16) bf g_oth[TT*LS],   g_otl[TT*LS];
__device__ float g_c[4*LS];
__device__ float g_m[LS];
__device__ float g_lc[LS];
__device__ float g_xhm[(size_t)GPX*896];
__device__ __align__(16) bf g_W1[(size_t)4*14*18*4096];
__device__ __align__(16) bf g_W2a[(size_t)4*36*4096];
__device__ __align__(16) bf g_W2b[4*4*4096];
__device__ __align__(16) bf g_W3[18*4096];
__device__ float g_b1[4*896], g_b2[4*128];

// ---------------- helpers ----------------
__device__ __forceinline__ uint32_t smem_u32(const void* p) {
    uint32_t a;
    asm("{ .reg .u64 t; cvta.to.shared.u64 t, %1; cvt.u32.u64 %0, t; }" : "=r"(a) : "l"(p));
    return a;
}
__device__ __forceinline__ float sigf(float v) { return 1.0f / (1.0f + expf(-v)); }
__device__ __forceinline__ void cpa16(uint32_t d, const void* s, uint32_t srcsz) {
    asm volatile("cp.async.cg.shared.global [%0], [%1], 16, %2;" :: "r"(d), "l"(s), "r"(srcsz));
}
__device__ __forceinline__ void cpa_commit() { asm volatile("cp.async.commit_group;" ::: "memory"); }
template<int N>
__device__ __forceinline__ void cpa_wait() { asm volatile("cp.async.wait_group %0;" :: "n"(N) : "memory"); }
__device__ __forceinline__ void ldm4(uint32_t* r, uint32_t a) {
    asm volatile("ldmatrix.sync.aligned.m8n8.x4.shared.b16 {%0,%1,%2,%3}, [%4];"
        : "=r"(r[0]), "=r"(r[1]), "=r"(r[2]), "=r"(r[3]) : "r"(a));
}
__device__ __forceinline__ void mma16816(float* d, const uint32_t* a, const uint32_t* b) {
    asm volatile("mma.sync.aligned.m16n8k16.row.col.f32.bf16.bf16.f32 "
        "{%0,%1,%2,%3}, {%4,%5,%6,%7}, {%8,%9}, {%0,%1,%2,%3};"
        : "+f"(d[0]), "+f"(d[1]), "+f"(d[2]), "+f"(d[3])
        : "r"(a[0]), "r"(a[1]), "r"(a[2]), "r"(a[3]), "r"(b[0]), "r"(b[1]));
}
// stage one 64-row x 32-K weight chunk (hi+lo planes) into a double buffer
__device__ __forceinline__ void stageW64(const bf* W, uint32_t Wb, int c, int tid) {
    const char* ws = (const char*)(W + (size_t)c * 4096);
    const uint32_t wb = Wb + (uint32_t)(c & 1) * 2 * 5120;
    for (int i = tid; i < 512; i += 256) {
        const int pl = i >= 256;
        const int j  = i - pl * 256;
        const int r = j >> 2, sg = j & 3;
        cpa16(wb + pl * 5120 + r * 80 + sg * 16,
              ws + pl * 4096 + r * 64 + sg * 16, 16);
    }
}

// =====================================================================
// bf16x3 implicit-GEMM conv via mma.sync.  M=64 co, N=PXT pixels.
// Halo-resident activation tile (reused by all taps), cp.async dbl-buffered
// weight stream.  EPI 0: xhm (gemm1)  EPI 1: gate2 (Wo)  EPI 2: decoder
// EPI 3: tanh(Wl) -> lc scratch
// =====================================================================
template<int CIW, int PXT, int TAPS, int EPI>
__global__ void __launch_bounds__(256) gemm_k(
    const bf* __restrict__ xH, const bf* __restrict__ xL,
    const bf* __restrict__ hH, const bf* __restrict__ hL,
    const bf* __restrict__ mH, const bf* __restrict__ mL,
    const bf* __restrict__ Wg, const float* __restrict__ bias,
    float* __restrict__ xhm, float* __restrict__ lcp,
    bf* __restrict__ o0h, bf* __restrict__ o0l,
    bf* __restrict__ o1h, bf* __restrict__ o1l,
    float* __restrict__ dec)
{
    constexpr int CPT    = CIW / 32;
    constexpr int NCH    = TAPS * CPT;
    constexpr int APITCH = CIW * 2 + 16;
    constexpr int SROWS  = (PXT / 32 + 2) * 34;
    constexpr int APLANE = SROWS * APITCH;
    constexpr int SEGS   = CIW / 8;
    constexpr int WPX    = PXT / 4;     // pixels per warp
    constexpr int NF     = WPX / 16;    // 16-px B fragments per warp

    extern __shared__ char smem[];
    const int tid = threadIdx.x, wid = tid >> 5, lane = tid & 31;
    const uint32_t sb = smem_u32(smem);
    const uint32_t Wb = sb + 2 * APLANE;

    const int mt = blockIdx.y;
    const bf *srcH, *srcL;
    if (EPI == 0) {
        if (mt < 7)       { srcH = xH; srcL = xL; }
        else if (mt < 11) { srcH = hH; srcL = hL; }
        else              { srcH = mH; srcL = mL; }
    } else { srcH = xH; srcL = xL; }
    const bf* W = Wg + (size_t)mt * NCH * 4096;

    const int px0 = blockIdx.x * PXT;
    const int img = px0 >> 10;
    const int y0  = (px0 & 1023) >> 5;

    // ---- stage A (once, halo, zero-filled borders) ----
    for (int i = tid; i < SROWS * SEGS; i += 256) {
        const int s = i / SEGS, seg = i % SEGS;
        const int yy = y0 + s / 34 - 1, xx = s % 34 - 1;
        const bool v = ((unsigned)yy < 32u) && ((unsigned)xx < 32u);
        const size_t off = v ? ((size_t)((img << 10) + yy * 32 + xx) * CIW + seg * 8) * 2 : 0;
        const uint32_t sz = v ? 16u : 0u;
        const uint32_t d = sb + (uint32_t)s * APITCH + seg * 16;
        cpa16(d,          (const char*)srcH + off, sz);
        cpa16(d + APLANE, (const char*)srcL + off, sz);
    }
    stageW64(W, Wb, 0, tid);
    cpa_commit();

    // ---- warp geometry ----
    const int wco = wid & 1, wpx = wid >> 1;
    const int arow = lane & 15, ahalf = lane >> 4;
    const int brow = (lane & 7) + ((lane >> 4) << 3);
    const int bhalf = (lane >> 3) & 1;
    int siteB[NF];
#pragma unroll
    for (int nf = 0; nf < NF; nf++) {
        const int base = wpx * WPX + nf * 16;
        siteB[nf] = ((base >> 5) + 1) * 34 + (base & 31) + 1 + brow;
    }

    float acc[2][2 * NF][4] = {};

    for (int c = 0; c < NCH; c++) {
        if (c + 1 < NCH) { stageW64(W, Wb, c + 1, tid); cpa_commit(); cpa_wait<1>(); }
        else             { cpa_wait<0>(); }
        __syncthreads();

        const int tap = c / CPT, ci0 = (c % CPT) * 32;
        const int sh = (TAPS == 1) ? 0 : ((tap / 3 - 1) * 34 + (tap % 3 - 1));
        const uint32_t wbase = Wb + (uint32_t)(c & 1) * 2 * 5120 + (uint32_t)(wco * 32) * 80;
        const uint32_t abk = sb + (uint32_t)(ci0 * 2) + (uint32_t)(bhalf * 16);

#pragma unroll
        for (int kf = 0; kf < 2; kf++) {
            uint32_t wh_[2][4], wl_[2][4];
#pragma unroll
            for (int mf = 0; mf < 2; mf++) {
                const uint32_t ad = wbase + (uint32_t)(mf * 16 + arow) * 80 + kf * 32 + ahalf * 16;
                ldm4(wh_[mf], ad);
                ldm4(wl_[mf], ad + 5120);
            }
#pragma unroll
            for (int nf = 0; nf < NF; nf++) {
                uint32_t bh_[4], bl_[4];
                const uint32_t ad = abk + (uint32_t)(siteB[nf] + sh) * APITCH + kf * 32;
                ldm4(bh_, ad);
                ldm4(bl_, ad + APLANE);
#pragma unroll
                for (int mf = 0; mf < 2; mf++)
#pragma unroll
                    for (int j = 0; j < 2; j++) {
                        mma16816(acc[mf][nf * 2 + j], wh_[mf], &bh_[j * 2]);
                        mma16816(acc[mf][nf * 2 + j], wh_[mf], &bl_[j * 2]);
                        mma16816(acc[mf][nf * 2 + j], wl_[mf], &bh_[j * 2]);
                    }
            }
        }
        __syncthreads();
    }

    // ---- transpose accumulators into SMEM ([px][co], pitch 68) ----
    float* Dt = (float*)smem;
    __syncthreads();
#pragma unroll
    for (int mf = 0; mf < 2; mf++)
#pragma unroll
        for (int n4 = 0; n4 < 2 * NF; n4++) {
            const int row = wco * 32 + mf * 16 + (lane >> 2);
            const int col = wpx * WPX + n4 * 8 + (lane & 3) * 2;
            Dt[col * 68 + row]           = acc[mf][n4][0];
            Dt[(col + 1) * 68 + row]     = acc[mf][n4][1];
            Dt[col * 68 + row + 8]       = acc[mf][n4][2];
            Dt[(col + 1) * 68 + row + 8] = acc[mf][n4][3];
        }
    __syncthreads();

    if (EPI == 0) {
        const int coG = mt * 64;
        for (int i = tid * 4; i < PXT * 64; i += 1024) {
            const int px = i >> 6, co = i & 63;
            float4 v = *(const float4*)&Dt[px * 68 + co];
            v.x += bias[coG + co];     v.y += bias[coG + co + 1];
            v.z += bias[coG + co + 2]; v.w += bias[coG + co + 3];
            *(float4*)&xhm[(size_t)(px0 + px) * 896 + coG + co] = v;
        }
    } else if (EPI == 1) {
        for (int i = tid; i < PXT * 64; i += 256) {
            const int px = i >> 6, ch = i & 63;
            const size_t g = (size_t)(px0 + px);
            const float oc = Dt[px * 68 + ch] + bias[ch];
            const float ot = sigf(oc + xhm[g * 896 + 384 + ch] + xhm[g * 896 + 640 + ch]);
            const float hv = ot * lcp[g * 64 + ch];
            const bf hi = __float2bfloat16(hv);
            const bf lo = __float2bfloat16(hv - __bfloat162float(hi));
            o0h[g * 64 + ch] = hi; o0l[g * 64 + ch] = lo;
            if (o1h) { o1h[g * 64 + ch] = hi; o1l[g * 64 + ch] = lo; }
        }
    } else if (EPI == 3) {
        for (int i = tid; i < PXT * 64; i += 256) {
            const int px = i >> 6, ch = i & 63;
            lcp[(size_t)(px0 + px) * 64 + ch] = tanhf(Dt[px * 68 + ch] + bias[ch]);
        }
    } else {  // EPI 2: decoder, sigmoid + depth-to-space
        const int t = px0 >> 13, b = (px0 >> 10) & 7;
        const size_t obase = (size_t)(b * TT + t) * 65536;
        for (int j = tid; j < PXT * 64; j += 256) {
            const int xx = j & 31, yy = (j >> 5) & 3, ch = j >> 7;
            const float v = sigf(Dt[(yy * 32 + xx) * 68 + ch] + bias[ch]);
            dec[obase + (size_t)((ch >> 3) * 32 + y0 + yy) * 256 + (ch & 7) * 32 + xx] = v;
        }
    }
}

// ---------------- gate 1 ----------------
__global__ void gate1_k(const float* __restrict__ xhm, float* __restrict__ c,
                        float* __restrict__ m, bf* __restrict__ memh,
                        bf* __restrict__ meml)
{
    const int idx = blockIdx.x * 256 + threadIdx.x;
    const int px = idx >> 6, ch = idx & 63;
    const float* v = xhm + (size_t)px * 896;
    const float it  = sigf(v[ch]        + v[448 + ch]);
    const float ft  = sigf(v[64 + ch]   + v[512 + ch]);
    const float gt  = tanhf(v[128 + ch] + v[576 + ch]);
    const float cn  = ft * c[idx] + it * gt;
    const float itp = sigf(v[192 + ch]  + v[704 + ch]);
    const float ftp = sigf(v[256 + ch]  + v[768 + ch]);
    const float gtp = tanhf(v[320 + ch] + v[832 + ch]);
    const float mn  = ftp * m[idx] + itp * gtp;
    c[idx] = cn; m[idx] = mn;
    const bf chi = __float2bfloat16(cn);
    const bf mhi = __float2bfloat16(mn);
    memh[(size_t)px * 128 + ch]      = chi;
    memh[(size_t)px * 128 + 64 + ch] = mhi;
    meml[(size_t)px * 128 + ch]      = __float2bfloat16(cn - __bfloat162float(chi));
    meml[(size_t)px * 128 + 64 + ch] = __float2bfloat16(mn - __bfloat162float(mhi));
}

// ---------------- gate1b: refresh m hi/lo planes for next layer's gemm1 ----
__global__ void gate1b_k(const float* __restrict__ m, bf* __restrict__ mh,
                         bf* __restrict__ ml)
{
    const int idx = blockIdx.x * 256 + threadIdx.x;
    const float mv = m[idx];
    const bf hi = __float2bfloat16(mv);
    mh[idx] = hi;
    ml[idx] = __float2bfloat16(mv - __bfloat162float(hi));
}

// ---------------- patch (space-to-depth, NHWC, bf16 split) ----------------
__global__ void patch_k(const float* __restrict__ x, bf* __restrict__ xh,
                        bf* __restrict__ xl)
{
    const int idx = blockIdx.x * 256 + threadIdx.x;
    const int ch = idx & 63, yx = (idx >> 6) & 1023;
    const int b = (idx >> 16) & 7, t = idx >> 19;
    const float v = x[(size_t)(b * INLEN + t) * 65536 +
                      (size_t)((ch >> 3) * 32 + (yx >> 5)) * 256 + (ch & 7) * 32 + (yx & 31)];
    const bf hi = __float2bfloat16(v);
    xh[idx] = hi;
    xl[idx] = __float2bfloat16(v - __bfloat162float(hi));
}

// ---------------- fused zero (one launch) ----------------
__global__ void zero_all(float4* hh, float4* hl, float4* mh, float4* ml,
                         float4* c, float4* m)
{
    const int i = blockIdx.x * 256 + threadIdx.x;
    const float4 z = make_float4(0.f, 0.f, 0.f, 0.f);
    if (i < 262144)       hh[i] = z;
    else if (i < 524288)  hl[i - 262144] = z;
    else if (i < 589824)  mh[i - 524288] = z;
    else if (i < 655360)  ml[i - 589824] = z;
    else if (i < 1179648) c[i - 655360] = z;
    else                  m[i - 1179648] = z;
}

// ---------------- weight prep ----------------
__global__ void prepW1_k(const float* __restrict__ Wx, const float* __restrict__ Wh,
                         const float* __restrict__ Wm, bf* __restrict__ dst)
{
    const int idx = blockIdx.x * 256 + threadIdx.x;
    const int kk = idx & 31, row = (idx >> 5) & 63;
    const int c = (idx >> 11) % 18, r2 = (idx >> 11) / 18;
    const int mt = r2 % 14, l = r2 / 14;
    const int co = mt * 64 + row, tap = c >> 1, ci = ((c & 1) << 5) + kk;
    float v;
    if (co < 448)      v = Wx[((size_t)(l * 448 + co) * 64 + ci) * 9 + tap];
    else if (co < 704) v = Wh[((size_t)(l * 256 + co - 448) * 64 + ci) * 9 + tap];
    else               v = Wm[((size_t)(l * 192 + co - 704) * 64 + ci) * 9 + tap];
    const bf hi = __float2bfloat16(v);
    const size_t base = ((size_t)(l * 14 + mt) * 18 + c) * 4096;
    dst[base + row * 32 + kk]        = hi;
    dst[base + 2048 + row * 32 + kk] = __float2bfloat16(v - __bfloat162float(hi));
}

__global__ void prepW2a_k(const float* __restrict__ Wo, bf* __restrict__ dst)
{
    const int idx = blockIdx.x * 256 + threadIdx.x;   // 4*36*2048
    const int kk = idx & 31, row = (idx >> 5) & 63;
    const int c = (idx >> 11) % 36, l = (idx >> 11) / 36;
    const int tap = c >> 2, ci = ((c & 3) << 5) + kk;
    const float v = Wo[((size_t)(l * 64 + row) * 128 + ci) * 9 + tap];
    const bf hi = __float2bfloat16(v);
    const size_t base = (size_t)(l * 36 + c) * 4096;
    dst[base + row * 32 + kk]        = hi;
    dst[base + 2048 + row * 32 + kk] = __float2bfloat16(v - __bfloat162float(hi));
}

__global__ void prep_rest_k(const float* __restrict__ Wl, const float* __restrict__ Wd,
                            const float* __restrict__ bx, const float* __restrict__ bh,
                            const float* __restrict__ bm, const float* __restrict__ bo,
                            const float* __restrict__ bl,
                            bf* __restrict__ dWl, bf* __restrict__ dWd,
                            float* __restrict__ b1, float* __restrict__ b2)
{
    const int idx = blockIdx.x * 256 + threadIdx.x;
    if (idx < 32768) {          // Wl: 4l x 4c x 64row x 32kk
        const int kk = idx & 31, row = (idx >> 5) & 63;
        const int c = (idx >> 11) & 3, l = idx >> 13;
        const float v = Wl[(size_t)(l * 64 + row) * 128 + c * 32 + kk];
        const bf hi = __float2bfloat16(v);
        const size_t base = (size_t)(l * 4 + c) * 4096;
        dWl[base + row * 32 + kk]        = hi;
        dWl[base + 2048 + row * 32 + kk] = __float2bfloat16(v - __bfloat162float(hi));
    } else if (idx < 69632) {   // Wd: 18c x 64row x 32kk
        const int j = idx - 32768;
        const int kk = j & 31, row = (j >> 5) & 63, c = j >> 11;
        const int tap = c >> 1, ci = ((c & 1) << 5) + kk;
        const float v = Wd[((size_t)row * 64 + ci) * 9 + tap];
        const bf hi = __float2bfloat16(v);
        const size_t base = (size_t)c * 4096;
        dWd[base + row * 32 + kk]        = hi;
        dWd[base + 2048 + row * 32 + kk] = __float2bfloat16(v - __bfloat162float(hi));
    } else if (idx < 73216) {   // b1: 4*896
        const int j = idx - 69632;
        const int l = j / 896, q = j % 896;
        b1[j] = q < 448 ? bx[l * 448 + q]
              : q < 704 ? bh[l * 256 + q - 448]
                        : bm[l * 192 + q - 704];
    } else if (idx < 73728) {   // b2: 4*128
        const int j = idx - 73216;
        const int l = j / 128, q = j % 128;
        b2[j] = q < 64 ? bo[l * 64 + q] : bl[l * 64 + q - 64];
    }
}

// =====================================================================
extern "C" void kernel_launch(void* const* d_in, const int* in_sizes, int n_in,
                              void* d_out, int out_size)
{
    const float* x  = (const float*)d_in[0];
    const float* Wx = (const float*)d_in[3];
    const float* bx = (const float*)d_in[4];
    const float* Wh = (const float*)d_in[5];
    const float* bh = (const float*)d_in[6];
    const float* Wm = (const float*)d_in[7];
    const float* bm = (const float*)d_in[8];
    const float* Wo = (const float*)d_in[9];
    const float* bo = (const float*)d_in[10];
    const float* Wl = (const float*)d_in[11];
    const float* bl = (const float*)d_in[12];
    const float* Wd = (const float*)d_in[13];
    const float* bd = (const float*)d_in[14];
    float* out = (float*)d_out;

    bf *xh, *xl, *hh, *hl, *mh, *ml, *memh, *meml, *oth, *otl, *W1, *W2a, *W2b, *W3;
    float *c, *m, *lc, *xhm, *b1, *b2;
    cudaGetSymbolAddress((void**)&xh,   g_xh);
    cudaGetSymbolAddress((void**)&xl,   g_xl);
    cudaGetSymbolAddress((void**)&hh,   g_hh);
    cudaGetSymbolAddress((void**)&hl,   g_hl);
    cudaGetSymbolAddress((void**)&mh,   g_mh);
    cudaGetSymbolAddress((void**)&ml,   g_ml);
    cudaGetSymbolAddress((void**)&memh, g_memh);
    cudaGetSymbolAddress((void**)&meml, g_meml);
    cudaGetSymbolAddress((void**)&oth,  g_oth);
    cudaGetSymbolAddress((void**)&otl,  g_otl);
    cudaGetSymbolAddress((void**)&c,    g_c);
    cudaGetSymbolAddress((void**)&m,    g_m);
    cudaGetSymbolAddress((void**)&lc,   g_lc);
    cudaGetSymbolAddress((void**)&xhm,  g_xhm);
    cudaGetSymbolAddress((void**)&W1,   g_W1);
    cudaGetSymbolAddress((void**)&W2a,  g_W2a);
    cudaGetSymbolAddress((void**)&W2b,  g_W2b);
    cudaGetSymbolAddress((void**)&W3,   g_W3);
    cudaGetSymbolAddress((void**)&b1,   g_b1);
    cudaGetSymbolAddress((void**)&b2,   g_b2);

    // smem: 2*APLANE + 4*5120 (W double buffer, hi+lo)
    const int SM1 = 2 * (340 * 144) + 20480;   // gemm1: CIW=64, PXT=256 -> 118400
    const int SM2 = 2 * (136 * 272) + 20480;   // gemm2: CIW=128, PXT=64 ->  94464
    const int SM3 = 2 * (204 * 144) + 20480;   // dec:   CIW=64, PXT=128 ->  79232
    cudaFuncSetAttribute(gemm_k<64, 256, 9, 0>,
                         cudaFuncAttributeMaxDynamicSharedMemorySize, SM1);
    cudaFuncSetAttribute(gemm_k<128, 64, 9, 1>,
                         cudaFuncAttributeMaxDynamicSharedMemorySize, SM2);
    cudaFuncSetAttribute(gemm_k<128, 64, 1, 3>,
                         cudaFuncAttributeMaxDynamicSharedMemorySize, SM2);
    cudaFuncSetAttribute(gemm_k<64, 128, 9, 2>,
                         cudaFuncAttributeMaxDynamicSharedMemorySize, SM3);

    // launches 0-4 (so ncu -s 5 profiles the first gemm1)
    zero_all<<<5120, 256>>>((float4*)hh, (float4*)hl, (float4*)mh, (float4*)ml,
                            (float4*)c, (float4*)m);
    patch_k<<<20480, 256>>>(x, xh, xl);
    prepW1_k<<<8064, 256>>>(Wx, Wh, Wm, W1);
    prepW2a_k<<<1152, 256>>>(Wo, W2a);
    prep_rest_k<<<288, 256>>>(Wl, Wd, bx, bh, bm, bo, bl, W2b, W3, b1, b2);

    for (int t = 0; t < TT; t++) {
        const bf* curh = (t < INLEN) ? (xh + (size_t)t * LS) : (oth + (size_t)(t - 1) * LS);
        const bf* curl = (t < INLEN) ? (xl + (size_t)t * LS) : (otl + (size_t)(t - 1) * LS);
        for (int l = 0; l < 4; l++) {
            const bf* inh = (l == 0) ? curh : (hh + (size_t)(l - 1) * LS);
            const bf* inl = (l == 0) ? curl : (hl + (size_t)(l - 1) * LS);
            gemm_k<64, 256, 9, 0><<<dim3(32, 14), 256, SM1>>>(
                inh, inl, hh + (size_t)l * LS, hl + (size_t)l * LS, mh, ml,
                W1 + (size_t)l * 14 * 18 * 4096, b1 + l * 896, xhm, nullptr,
                nullptr, nullptr, nullptr, nullptr, nullptr);
            gate1_k<<<2048, 256>>>(xhm, c + (size_t)l * LS, m, memh, meml);
            gate1b_k<<<2048, 256>>>(m, mh, ml);
            gemm_k<128, 64, 1, 3><<<dim3(128, 1), 256, SM2>>>(
                memh, meml, nullptr, nullptr, nullptr, nullptr,
                W2b + (size_t)l * 4 * 4096, b2 + l * 128 + 64, nullptr, lc,
                nullptr, nullptr, nullptr, nullptr, nullptr);
            gemm_k<128, 64, 9, 1><<<dim3(128, 1), 256, SM2>>>(
                memh, meml, nullptr, nullptr, nullptr, nullptr,
                W2a + (size_t)l * 36 * 4096, b2 + l * 128, xhm, lc,
                hh + (size_t)l * LS, hl + (size_t)l * LS,
                (l == 3) ? (oth + (size_t)t * LS) : nullptr,
                (l == 3) ? (otl + (size_t)t * LS) : nullptr, nullptr);
        }
    }

    gemm_k<64, 128, 9, 2><<<dim3(1216, 1), 256, SM3>>>(
        oth, otl, nullptr, nullptr, nullptr, nullptr,
        W3, bd, nullptr, nullptr, nullptr, nullptr, nullptr, nullptr, out);
}

// round 8
// speedup vs baseline: 1.7120x; 1.7120x over previous
#include <cuda_runtime.h>
#include <cuda_bf16.h>
#include <math.h>
#include <stdint.h>

#define TT    19
#define INLEN 10
#define GPX   8192
#define LS    (GPX*64)
typedef __nv_bfloat16 bf;

// ---------------- device scratch ----------------
__device__ __align__(16) bf g_xh[INLEN*LS], g_xl[INLEN*LS];
__device__ __align__(16) bf g_hh[4*LS],     g_hl[4*LS];
__device__ __align__(16) bf g_mh[LS],       g_ml[LS];
__device__ __align__(16) bf g_memh[GPX*128], g_meml[GPX*128];
__device__ __align__(16) bf g_oth[TT*LS],   g_otl[TT*LS];
__device__ float g_c[4*LS];
__device__ float g_m[LS];
__device__ float g_xhm[(size_t)GPX*896];
__device__ __align__(16) bf g_W1[(size_t)4*14*18*2048];   // hi-only weights
__device__ __align__(16) bf g_W2[(size_t)4*36*4096];
__device__ __align__(16) bf g_W3[18*2048];
__device__ float g_b1[4*896], g_b2[4*128];

// ---------------- helpers ----------------
__device__ __forceinline__ uint32_t smem_u32(const void* p) {
    uint32_t a;
    asm("{ .reg .u64 t; cvta.to.shared.u64 t, %1; cvt.u32.u64 %0, t; }" : "=r"(a) : "l"(p));
    return a;
}
__device__ __forceinline__ float sigf(float v) { return 1.0f / (1.0f + expf(-v)); }
__device__ __forceinline__ void cpa16(uint32_t d, const void* s, uint32_t srcsz) {
    asm volatile("cp.async.cg.shared.global [%0], [%1], 16, %2;" :: "r"(d), "l"(s), "r"(srcsz));
}
__device__ __forceinline__ void cpa_commit() { asm volatile("cp.async.commit_group;" ::: "memory"); }
template<int N>
__device__ __forceinline__ void cpa_wait() { asm volatile("cp.async.wait_group %0;" :: "n"(N) : "memory"); }
__device__ __forceinline__ void ldm4(uint32_t* r, uint32_t a) {
    asm volatile("ldmatrix.sync.aligned.m8n8.x4.shared.b16 {%0,%1,%2,%3}, [%4];"
        : "=r"(r[0]), "=r"(r[1]), "=r"(r[2]), "=r"(r[3]) : "r"(a));
}
__device__ __forceinline__ void mma16816(float* d, const uint32_t* a, const uint32_t* b) {
    asm volatile("mma.sync.aligned.m16n8k16.row.col.f32.bf16.bf16.f32 "
        "{%0,%1,%2,%3}, {%4,%5,%6,%7}, {%8,%9}, {%0,%1,%2,%3};"
        : "+f"(d[0]), "+f"(d[1]), "+f"(d[2]), "+f"(d[3])
        : "r"(a[0]), "r"(a[1]), "r"(a[2]), "r"(a[3]), "r"(b[0]), "r"(b[1]));
}
// stage one COT-row x 32-K weight chunk (hi only) into a double buffer
template<int COT>
__device__ __forceinline__ void stageW(const bf* W, uint32_t Wb, int c, int tid) {
    const char* ws = (const char*)(W + (size_t)c * COT * 32);
    const uint32_t wb = Wb + (uint32_t)(c & 1) * (COT * 80);
    for (int i = tid; i < COT * 4; i += 256) {
        const int r = i >> 2, sg = i & 3;
        cpa16(wb + r * 80 + sg * 16, ws + r * 64 + sg * 16, 16);
    }
}

// =====================================================================
// bf16x2 implicit-GEMM conv via mma.sync (bf16 weights, split activations).
// Halo-resident activation tile (reused by all 9 taps), cp.async dbl-
// buffered weight stream.  EPI 0: xhm  EPI 1: fused gate2  EPI 2: decoder
// =====================================================================
template<int CIW, int COT, int PXT, int EPI>
__global__ void __launch_bounds__(256) gemm_k(
    const bf* __restrict__ xH, const bf* __restrict__ xL,
    const bf* __restrict__ hH, const bf* __restrict__ hL,
    const bf* __restrict__ mH, const bf* __restrict__ mL,
    const bf* __restrict__ Wg, const float* __restrict__ bias,
    float* __restrict__ xhm,
    bf* __restrict__ o0h, bf* __restrict__ o0l,
    bf* __restrict__ o1h, bf* __restrict__ o1l,
    float* __restrict__ dec)
{
    constexpr int NCH    = 9 * CIW / 32;
    constexpr int CPT    = CIW / 32;
    constexpr int APITCH = CIW * 2 + 16;
    constexpr int SROWS  = (PXT / 32 + 2) * 34;
    constexpr int APLANE = SROWS * APITCH;
    constexpr int WPLANE = COT * 80;
    constexpr int SEGS   = CIW / 8;

    extern __shared__ char smem[];
    const int tid = threadIdx.x, wid = tid >> 5, lane = tid & 31;
    const uint32_t sb = smem_u32(smem);
    const uint32_t Wb = sb + 2 * APLANE;

    const int mt = blockIdx.y;
    const bf *srcH, *srcL;
    if (EPI == 0) {
        if (mt < 7)       { srcH = xH; srcL = xL; }
        else if (mt < 11) { srcH = hH; srcL = hL; }
        else              { srcH = mH; srcL = mL; }
    } else { srcH = xH; srcL = xL; }
    const bf* W = Wg + (size_t)mt * NCH * COT * 32;

    const int px0 = blockIdx.x * PXT;
    const int img = px0 >> 10;
    const int y0  = (px0 & 1023) >> 5;

    // ---- stage A (once, halo, zero-filled borders) ----
    for (int i = tid; i < SROWS * SEGS; i += 256) {
        const int s = i / SEGS, seg = i % SEGS;
        const int yy = y0 + s / 34 - 1, xx = s % 34 - 1;
        const bool v = ((unsigned)yy < 32u) && ((unsigned)xx < 32u);
        const size_t off = v ? ((size_t)((img << 10) + yy * 32 + xx) * CIW + seg * 8) * 2 : 0;
        const uint32_t sz = v ? 16u : 0u;
        const uint32_t d = sb + (uint32_t)s * APITCH + seg * 16;
        cpa16(d,          (const char*)srcH + off, sz);
        cpa16(d + APLANE, (const char*)srcL + off, sz);
    }
    stageW<COT>(W, Wb, 0, tid);
    cpa_commit();

    // ---- warp geometry ----
    int wco, wpx;
    if (COT == 64) { wco = wid & 1; wpx = wid >> 1; }
    else           { wco = wid & 3; wpx = wid >> 2; }
    const int arow = lane & 15, ahalf = lane >> 4;
    const int brow = (lane & 7) + ((lane >> 4) << 3);
    const int bhalf = (lane >> 3) & 1;

    float acc[2][4][4] = {};

    for (int c = 0; c < NCH; c++) {
        if (c + 1 < NCH) { stageW<COT>(W, Wb, c + 1, tid); cpa_commit(); cpa_wait<1>(); }
        else             { cpa_wait<0>(); }
        __syncthreads();

        const int tap = c / CPT, ci0 = (c % CPT) * 32;
        const int dy = tap / 3 - 1, dx = tap % 3 - 1;
        const uint32_t abase = sb + (uint32_t)((wpx + 1 + dy) * 34 + 1 + dx) * APITCH + ci0 * 2;
        const uint32_t wbase = Wb + (uint32_t)(c & 1) * WPLANE + (uint32_t)(wco * 32) * 80;

#pragma unroll
        for (int kf = 0; kf < 2; kf++) {
            uint32_t wh_[2][4];
#pragma unroll
            for (int mf = 0; mf < 2; mf++) {
                const uint32_t ad = wbase + (uint32_t)(mf * 16 + arow) * 80 + kf * 32 + ahalf * 16;
                ldm4(wh_[mf], ad);
            }
#pragma unroll
            for (int nf = 0; nf < 2; nf++) {
                uint32_t bh_[4], bl_[4];
                const uint32_t ad = abase + (uint32_t)(nf * 16 + brow) * APITCH + kf * 32 + bhalf * 16;
                ldm4(bh_, ad);
                ldm4(bl_, ad + APLANE);
#pragma unroll
                for (int mf = 0; mf < 2; mf++)
#pragma unroll
                    for (int j = 0; j < 2; j++) {
                        mma16816(acc[mf][nf * 2 + j], wh_[mf], &bh_[j * 2]);
                        mma16816(acc[mf][nf * 2 + j], wh_[mf], &bl_[j * 2]);
                    }
            }
        }
        __syncthreads();
    }

    // ---- transpose accumulators into SMEM ([px][co]) ----
    float* Dt = (float*)smem;
    constexpr int P = (EPI == 1) ? 132 : 68;
    __syncthreads();
#pragma unroll
    for (int mf = 0; mf < 2; mf++)
#pragma unroll
        for (int n4 = 0; n4 < 4; n4++) {
            const int row = wco * 32 + mf * 16 + (lane >> 2);
            const int col = wpx * 32 + n4 * 8 + (lane & 3) * 2;
            Dt[col * P + row]           = acc[mf][n4][0];
            Dt[(col + 1) * P + row]     = acc[mf][n4][1];
            Dt[col * P + row + 8]       = acc[mf][n4][2];
            Dt[(col + 1) * P + row + 8] = acc[mf][n4][3];
        }
    __syncthreads();

    if (EPI == 0) {
        const int coG = mt * 64;
        for (int i = tid * 4; i < PXT * 64; i += 1024) {
            const int px = i >> 6, co = i & 63;
            float4 v = *(const float4*)&Dt[px * 68 + co];
            v.x += bias[coG + co];     v.y += bias[coG + co + 1];
            v.z += bias[coG + co + 2]; v.w += bias[coG + co + 3];
            *(float4*)&xhm[(size_t)(px0 + px) * 896 + coG + co] = v;
        }
    } else if (EPI == 1) {
        for (int i = tid; i < 64 * 64; i += 256) {
            const int px = i >> 6, ch = i & 63;
            const size_t g = (size_t)(px0 + px);
            const float oc = Dt[px * 132 + ch] + bias[ch];
            const float lc = Dt[px * 132 + 64 + ch] + bias[64 + ch];
            const float ot = sigf(oc + xhm[g * 896 + 384 + ch] + xhm[g * 896 + 640 + ch]);
            const float hv = ot * tanhf(lc);
            const bf hi = __float2bfloat16(hv);
            const bf lo = __float2bfloat16(hv - __bfloat162float(hi));
            o0h[g * 64 + ch] = hi; o0l[g * 64 + ch] = lo;
            if (o1h) { o1h[g * 64 + ch] = hi; o1l[g * 64 + ch] = lo; }
        }
    } else {
        const int t = px0 >> 13, b = (px0 >> 10) & 7;
        const size_t obase = (size_t)(b * TT + t) * 65536;
        for (int j = tid; j < 8192; j += 256) {
            const int xx = j & 31, yy = (j >> 5) & 3, ch = j >> 7;
            const float v = sigf(Dt[(yy * 32 + xx) * 68 + ch] + bias[ch]);
            dec[obase + (size_t)((ch >> 3) * 32 + y0 + yy) * 256 + (ch & 7) * 32 + xx] = v;
        }
    }
}

// ---------------- gate 1 ----------------
__global__ void gate1_k(const float* __restrict__ xhm, float* __restrict__ c,
                        float* __restrict__ m, bf* __restrict__ memh,
                        bf* __restrict__ meml, bf* __restrict__ mh,
                        bf* __restrict__ ml)
{
    const int idx = blockIdx.x * 256 + threadIdx.x;
    const int px = idx >> 6, ch = idx & 63;
    const float* v = xhm + (size_t)px * 896;
    const float it  = sigf(v[ch]        + v[448 + ch]);
    const float ft  = sigf(v[64 + ch]   + v[512 + ch]);
    const float gt  = tanhf(v[128 + ch] + v[576 + ch]);
    const float cn  = ft * c[idx] + it * gt;
    const float itp = sigf(v[192 + ch]  + v[704 + ch]);
    const float ftp = sigf(v[256 + ch]  + v[768 + ch]);
    const float gtp = tanhf(v[320 + ch] + v[832 + ch]);
    const float mn  = ftp * m[idx] + itp * gtp;
    c[idx] = cn; m[idx] = mn;
    const bf chi = __float2bfloat16(cn);
    const bf mhi = __float2bfloat16(mn);
    memh[(size_t)px * 128 + ch]      = chi;
    memh[(size_t)px * 128 + 64 + ch] = mhi;
    meml[(size_t)px * 128 + ch]      = __float2bfloat16(cn - __bfloat162float(chi));
    meml[(size_t)px * 128 + 64 + ch] = __float2bfloat16(mn - __bfloat162float(mhi));
    mh[idx] = mhi;
    ml[idx] = __float2bfloat16(mn - __bfloat162float(mhi));
}

// ---------------- patch (space-to-depth, NHWC, bf16 split) ----------------
__global__ void patch_k(const float* __restrict__ x, bf* __restrict__ xh,
                        bf* __restrict__ xl)
{
    const int idx = blockIdx.x * 256 + threadIdx.x;
    const int ch = idx & 63, yx = (idx >> 6) & 1023;
    const int b = (idx >> 16) & 7, t = idx >> 19;
    const float v = x[(size_t)(b * INLEN + t) * 65536 +
                      (size_t)((ch >> 3) * 32 + (yx >> 5)) * 256 + (ch & 7) * 32 + (yx & 31)];
    const bf hi = __float2bfloat16(v);
    xh[idx] = hi;
    xl[idx] = __float2bfloat16(v - __bfloat162float(hi));
}

// ---------------- fused zero (one launch) ----------------
__global__ void zero_all(float4* hh, float4* hl, float4* mh, float4* ml,
                         float4* c, float4* m)
{
    const int i = blockIdx.x * 256 + threadIdx.x;
    const float4 z = make_float4(0.f, 0.f, 0.f, 0.f);
    if (i < 262144)       hh[i] = z;
    else if (i < 524288)  hl[i - 262144] = z;
    else if (i < 589824)  mh[i - 524288] = z;
    else if (i < 655360)  ml[i - 589824] = z;
    else if (i < 1179648) c[i - 655360] = z;
    else                  m[i - 1179648] = z;
}

// ---------------- weight prep (hi-only bf16) ----------------
__global__ void prepW1_k(const float* __restrict__ Wx, const float* __restrict__ Wh,
                         const float* __restrict__ Wm, bf* __restrict__ dst)
{
    const int idx = blockIdx.x * 256 + threadIdx.x;   // 4*14*18*2048
    const int kk = idx & 31, row = (idx >> 5) & 63;
    const int c = (idx >> 11) % 18, r2 = (idx >> 11) / 18;
    const int mt = r2 % 14, l = r2 / 14;
    const int co = mt * 64 + row, tap = c >> 1, ci = ((c & 1) << 5) + kk;
    float v;
    if (co < 448)      v = Wx[((size_t)(l * 448 + co) * 64 + ci) * 9 + tap];
    else if (co < 704) v = Wh[((size_t)(l * 256 + co - 448) * 64 + ci) * 9 + tap];
    else               v = Wm[((size_t)(l * 192 + co - 704) * 64 + ci) * 9 + tap];
    dst[((size_t)(l * 14 + mt) * 18 + c) * 2048 + row * 32 + kk] = __float2bfloat16(v);
}

__global__ void prepW2_k(const float* __restrict__ Wo, const float* __restrict__ Wl,
                         bf* __restrict__ dst)
{
    const int idx = blockIdx.x * 256 + threadIdx.x;   // 4*36*4096
    const int kk = idx & 31, row = (idx >> 5) & 127;
    const int c = (idx >> 12) % 36, l = (idx >> 12) / 36;
    const int tap = c >> 2, ci = ((c & 3) << 5) + kk;
    float v = 0.f;
    if (row < 64)      v = Wo[((size_t)(l * 64 + row) * 128 + ci) * 9 + tap];
    else if (tap == 4) v = Wl[(size_t)(l * 64 + row - 64) * 128 + ci];
    dst[((size_t)(l * 36 + c)) * 4096 + row * 32 + kk] = __float2bfloat16(v);
}

__global__ void prep_rest_k(const float* __restrict__ Wd,
                            const float* __restrict__ bx, const float* __restrict__ bh,
                            const float* __restrict__ bm, const float* __restrict__ bo,
                            const float* __restrict__ bl,
                            bf* __restrict__ dWd,
                            float* __restrict__ b1, float* __restrict__ b2)
{
    const int idx = blockIdx.x * 256 + threadIdx.x;
    if (idx < 36864) {          // Wd: 18c x 64row x 32kk
        const int kk = idx & 31, row = (idx >> 5) & 63, c = idx >> 11;
        const int tap = c >> 1, ci = ((c & 1) << 5) + kk;
        dWd[(size_t)c * 2048 + row * 32 + kk] =
            __float2bfloat16(Wd[((size_t)row * 64 + ci) * 9 + tap]);
    } else if (idx < 40448) {   // b1: 4*896
        const int j = idx - 36864;
        const int l = j / 896, q = j % 896;
        b1[j] = q < 448 ? bx[l * 448 + q]
              : q < 704 ? bh[l * 256 + q - 448]
                        : bm[l * 192 + q - 704];
    } else if (idx < 40960) {   // b2: 4*128
        const int j = idx - 40448;
        const int l = j / 128, q = j % 128;
        b2[j] = q < 64 ? bo[l * 64 + q] : bl[l * 64 + q - 64];
    }
}

// =====================================================================
extern "C" void kernel_launch(void* const* d_in, const int* in_sizes, int n_in,
                              void* d_out, int out_size)
{
    const float* x  = (const float*)d_in[0];
    const float* Wx = (const float*)d_in[3];
    const float* bx = (const float*)d_in[4];
    const float* Wh = (const float*)d_in[5];
    const float* bh = (const float*)d_in[6];
    const float* Wm = (const float*)d_in[7];
    const float* bm = (const float*)d_in[8];
    const float* Wo = (const float*)d_in[9];
    const float* bo = (const float*)d_in[10];
    const float* Wl = (const float*)d_in[11];
    const float* bl = (const float*)d_in[12];
    const float* Wd = (const float*)d_in[13];
    const float* bd = (const float*)d_in[14];
    float* out = (float*)d_out;

    bf *xh, *xl, *hh, *hl, *mh, *ml, *memh, *meml, *oth, *otl, *W1, *W2, *W3;
    float *c, *m, *xhm, *b1, *b2;
    cudaGetSymbolAddress((void**)&xh,   g_xh);
    cudaGetSymbolAddress((void**)&xl,   g_xl);
    cudaGetSymbolAddress((void**)&hh,   g_hh);
    cudaGetSymbolAddress((void**)&hl,   g_hl);
    cudaGetSymbolAddress((void**)&mh,   g_mh);
    cudaGetSymbolAddress((void**)&ml,   g_ml);
    cudaGetSymbolAddress((void**)&memh, g_memh);
    cudaGetSymbolAddress((void**)&meml, g_meml);
    cudaGetSymbolAddress((void**)&oth,  g_oth);
    cudaGetSymbolAddress((void**)&otl,  g_otl);
    cudaGetSymbolAddress((void**)&c,    g_c);
    cudaGetSymbolAddress((void**)&m,    g_m);
    cudaGetSymbolAddress((void**)&xhm,  g_xhm);
    cudaGetSymbolAddress((void**)&W1,   g_W1);
    cudaGetSymbolAddress((void**)&W2,   g_W2);
    cudaGetSymbolAddress((void**)&W3,   g_W3);
    cudaGetSymbolAddress((void**)&b1,   g_b1);
    cudaGetSymbolAddress((void**)&b2,   g_b2);

    // smem: 2*APLANE + 2*WPLANE (hi-only weight double buffer)
    const int SM1 = 2 * (204 * 144) + 2 * 5120;    // 68992 -> 3 CTAs/SM
    const int SM2 = 2 * (136 * 272) + 2 * 10240;   // 94464 -> 2 CTAs/SM
    cudaFuncSetAttribute(gemm_k<64, 64, 128, 0>,
                         cudaFuncAttributeMaxDynamicSharedMemorySize, SM1);
    cudaFuncSetAttribute(gemm_k<128, 128, 64, 1>,
                         cudaFuncAttributeMaxDynamicSharedMemorySize, SM2);
    cudaFuncSetAttribute(gemm_k<64, 64, 128, 2>,
                         cudaFuncAttributeMaxDynamicSharedMemorySize, SM1);

    // launches 0-4 (so ncu -s 5 profiles the first gemm1)
    zero_all<<<5120, 256>>>((float4*)hh, (float4*)hl, (float4*)mh, (float4*)ml,
                            (float4*)c, (float4*)m);
    patch_k<<<20480, 256>>>(x, xh, xl);
    prepW1_k<<<8064, 256>>>(Wx, Wh, Wm, W1);
    prepW2_k<<<2304, 256>>>(Wo, Wl, W2);
    prep_rest_k<<<160, 256>>>(Wd, bx, bh, bm, bo, bl, W3, b1, b2);

    for (int t = 0; t < TT; t++) {
        const bf* curh = (t < INLEN) ? (xh + (size_t)t * LS) : (oth + (size_t)(t - 1) * LS);
        const bf* curl = (t < INLEN) ? (xl + (size_t)t * LS) : (otl + (size_t)(t - 1) * LS);
        for (int l = 0; l < 4; l++) {
            const bf* inh = (l == 0) ? curh : (hh + (size_t)(l - 1) * LS);
            const bf* inl = (l == 0) ? curl : (hl + (size_t)(l - 1) * LS);
            gemm_k<64, 64, 128, 0><<<dim3(64, 14), 256, SM1>>>(
                inh, inl, hh + (size_t)l * LS, hl + (size_t)l * LS, mh, ml,
                W1 + (size_t)l * 14 * 18 * 2048, b1 + l * 896, xhm,
                nullptr, nullptr, nullptr, nullptr, nullptr);
            gate1_k<<<2048, 256>>>(xhm, c + (size_t)l * LS, m, memh, meml, mh, ml);
            gemm_k<128, 128, 64, 1><<<dim3(128, 1), 256, SM2>>>(
                memh, meml, nullptr, nullptr, nullptr, nullptr,
                W2 + (size_t)l * 36 * 4096, b2 + l * 128, xhm,
                hh + (size_t)l * LS, hl + (size_t)l * LS,
                (l == 3) ? (oth + (size_t)t * LS) : nullptr,
                (l == 3) ? (otl + (size_t)t * LS) : nullptr, nullptr);
        }
    }

    gemm_k<64, 64, 128, 2><<<dim3(1216, 1), 256, SM1>>>(
        oth, otl, nullptr, nullptr, nullptr, nullptr,
        W3, bd, nullptr, nullptr, nullptr, nullptr, nullptr, out);
}

// round 9
// speedup vs baseline: 2.3145x; 1.3519x over previous
#include <cuda_runtime.h>
#include <cuda_bf16.h>
#include <math.h>
#include <stdint.h>

#define TT    19
#define INLEN 10
#define GPX   8192
#define LS    (GPX*64)
typedef __nv_bfloat16 bf;

// ---------------- device scratch (all activations pure bf16, NHWC) ----------------
__device__ __align__(16) bf g_xh[INLEN*LS];
__device__ __align__(16) bf g_hh[4*LS];
__device__ __align__(16) bf g_mh[LS];
__device__ __align__(16) bf g_memh[GPX*128];
__device__ __align__(16) bf g_oth[TT*LS];
__device__ float g_c[4*LS];
__device__ float g_m[LS];
__device__ float g_xhm[(size_t)GPX*896];
__device__ __align__(16) bf g_W1[(size_t)4*14*18*2048];
__device__ __align__(16) bf g_W2[(size_t)4*36*4096];
__device__ __align__(16) bf g_W3[18*2048];
__device__ float g_b1[4*896], g_b2[4*128];

// ---------------- helpers ----------------
__device__ __forceinline__ uint32_t smem_u32(const void* p) {
    uint32_t a;
    asm("{ .reg .u64 t; cvta.to.shared.u64 t, %1; cvt.u32.u64 %0, t; }" : "=r"(a) : "l"(p));
    return a;
}
__device__ __forceinline__ float sigf(float v) { return 1.0f / (1.0f + expf(-v)); }
__device__ __forceinline__ void cpa16(uint32_t d, const void* s, uint32_t srcsz) {
    asm volatile("cp.async.cg.shared.global [%0], [%1], 16, %2;" :: "r"(d), "l"(s), "r"(srcsz));
}
__device__ __forceinline__ void cpa_commit() { asm volatile("cp.async.commit_group;" ::: "memory"); }
template<int N>
__device__ __forceinline__ void cpa_wait() { asm volatile("cp.async.wait_group %0;" :: "n"(N) : "memory"); }
__device__ __forceinline__ void ldm4(uint32_t* r, uint32_t a) {
    asm volatile("ldmatrix.sync.aligned.m8n8.x4.shared.b16 {%0,%1,%2,%3}, [%4];"
        : "=r"(r[0]), "=r"(r[1]), "=r"(r[2]), "=r"(r[3]) : "r"(a));
}
__device__ __forceinline__ void mma16816(float* d, const uint32_t* a, const uint32_t* b) {
    asm volatile("mma.sync.aligned.m16n8k16.row.col.f32.bf16.bf16.f32 "
        "{%0,%1,%2,%3}, {%4,%5,%6,%7}, {%8,%9}, {%0,%1,%2,%3};"
        : "+f"(d[0]), "+f"(d[1]), "+f"(d[2]), "+f"(d[3])
        : "r"(a[0]), "r"(a[1]), "r"(a[2]), "r"(a[3]), "r"(b[0]), "r"(b[1]));
}
template<int COT>
__device__ __forceinline__ void stageW(const bf* W, uint32_t Wb, int c, int tid) {
    const char* ws = (const char*)(W + (size_t)c * COT * 32);
    const uint32_t wb = Wb + (uint32_t)(c & 1) * (COT * 80);
    for (int i = tid; i < COT * 4; i += 256) {
        const int r = i >> 2, sg = i & 3;
        cpa16(wb + r * 80 + sg * 16, ws + r * 64 + sg * 16, 16);
    }
}

// =====================================================================
// Pure-bf16 implicit-GEMM conv via mma.sync.
// Halo-resident activation tile (reused by all 9 taps), cp.async dbl-
// buffered weight stream.  EPI 0: xhm  EPI 1: fused gate2  EPI 2: decoder
// =====================================================================
template<int CIW, int COT, int PXT, int EPI>
__global__ void __launch_bounds__(256) gemm_k(
    const bf* __restrict__ xH, const bf* __restrict__ hH, const bf* __restrict__ mH,
    const bf* __restrict__ Wg, const float* __restrict__ bias,
    float* __restrict__ xhm,
    bf* __restrict__ o0h, bf* __restrict__ o1h,
    float* __restrict__ dec)
{
    constexpr int NCH    = 9 * CIW / 32;
    constexpr int CPT    = CIW / 32;
    constexpr int APITCH = CIW * 2 + 16;
    constexpr int SROWS  = (PXT / 32 + 2) * 34;
    constexpr int APLANE = SROWS * APITCH;
    constexpr int WPLANE = COT * 80;
    constexpr int SEGS   = CIW / 8;

    extern __shared__ char smem[];
    const int tid = threadIdx.x, wid = tid >> 5, lane = tid & 31;
    const uint32_t sb = smem_u32(smem);
    const uint32_t Wb = sb + APLANE;

    const int mt = blockIdx.y;
    const bf* srcH;
    if (EPI == 0) {
        if (mt < 7)       srcH = xH;
        else if (mt < 11) srcH = hH;
        else              srcH = mH;
    } else srcH = xH;
    const bf* W = Wg + (size_t)mt * NCH * COT * 32;

    const int px0 = blockIdx.x * PXT;
    const int img = px0 >> 10;
    const int y0  = (px0 & 1023) >> 5;

    // ---- stage A (once, halo, zero-filled borders) ----
    for (int i = tid; i < SROWS * SEGS; i += 256) {
        const int s = i / SEGS, seg = i % SEGS;
        const int yy = y0 + s / 34 - 1, xx = s % 34 - 1;
        const bool v = ((unsigned)yy < 32u) && ((unsigned)xx < 32u);
        const size_t off = v ? ((size_t)((img << 10) + yy * 32 + xx) * CIW + seg * 8) * 2 : 0;
        cpa16(sb + (uint32_t)s * APITCH + seg * 16, (const char*)srcH + off, v ? 16u : 0u);
    }
    stageW<COT>(W, Wb, 0, tid);
    cpa_commit();

    // ---- warp geometry ----
    int wco, wpx;
    if (COT == 64) { wco = wid & 1; wpx = wid >> 1; }
    else           { wco = wid & 3; wpx = wid >> 2; }
    const int arow = lane & 15, ahalf = lane >> 4;
    const int brow = (lane & 7) + ((lane >> 4) << 3);
    const int bhalf = (lane >> 3) & 1;

    float acc[2][4][4] = {};

    for (int c = 0; c < NCH; c++) {
        if (c + 1 < NCH) { stageW<COT>(W, Wb, c + 1, tid); cpa_commit(); cpa_wait<1>(); }
        else             { cpa_wait<0>(); }
        __syncthreads();

        const int tap = c / CPT, ci0 = (c % CPT) * 32;
        const int dy = tap / 3 - 1, dx = tap % 3 - 1;
        const uint32_t abase = sb + (uint32_t)((wpx + 1 + dy) * 34 + 1 + dx) * APITCH + ci0 * 2;
        const uint32_t wbase = Wb + (uint32_t)(c & 1) * WPLANE + (uint32_t)(wco * 32) * 80;

#pragma unroll
        for (int kf = 0; kf < 2; kf++) {
            uint32_t wh_[2][4];
#pragma unroll
            for (int mf = 0; mf < 2; mf++) {
                const uint32_t ad = wbase + (uint32_t)(mf * 16 + arow) * 80 + kf * 32 + ahalf * 16;
                ldm4(wh_[mf], ad);
            }
#pragma unroll
            for (int nf = 0; nf < 2; nf++) {
                uint32_t bh_[4];
                const uint32_t ad = abase + (uint32_t)(nf * 16 + brow) * APITCH + kf * 32 + bhalf * 16;
                ldm4(bh_, ad);
#pragma unroll
                for (int mf = 0; mf < 2; mf++)
#pragma unroll
                    for (int j = 0; j < 2; j++)
                        mma16816(acc[mf][nf * 2 + j], wh_[mf], &bh_[j * 2]);
            }
        }
        __syncthreads();
    }

    // ---- transpose accumulators into SMEM ([px][co]) ----
    float* Dt = (float*)smem;
    constexpr int P = (EPI == 1) ? 132 : 68;
    __syncthreads();
#pragma unroll
    for (int mf = 0; mf < 2; mf++)
#pragma unroll
        for (int n4 = 0; n4 < 4; n4++) {
            const int row = wco * 32 + mf * 16 + (lane >> 2);
            const int col = wpx * 32 + n4 * 8 + (lane & 3) * 2;
            Dt[col * P + row]           = acc[mf][n4][0];
            Dt[(col + 1) * P + row]     = acc[mf][n4][1];
            Dt[col * P + row + 8]       = acc[mf][n4][2];
            Dt[(col + 1) * P + row + 8] = acc[mf][n4][3];
        }
    __syncthreads();

    if (EPI == 0) {
        const int coG = mt * 64;
        for (int i = tid * 4; i < PXT * 64; i += 1024) {
            const int px = i >> 6, co = i & 63;
            float4 v = *(const float4*)&Dt[px * 68 + co];
            v.x += bias[coG + co];     v.y += bias[coG + co + 1];
            v.z += bias[coG + co + 2]; v.w += bias[coG + co + 3];
            *(float4*)&xhm[(size_t)(px0 + px) * 896 + coG + co] = v;
        }
    } else if (EPI == 1) {
        for (int i = tid; i < 64 * 64; i += 256) {
            const int px = i >> 6, ch = i & 63;
            const size_t g = (size_t)(px0 + px);
            const float oc = Dt[px * 132 + ch] + bias[ch];
            const float lc = Dt[px * 132 + 64 + ch] + bias[64 + ch];
            const float ot = sigf(oc + xhm[g * 896 + 384 + ch] + xhm[g * 896 + 640 + ch]);
            const float hv = ot * tanhf(lc);
            const bf hi = __float2bfloat16(hv);
            o0h[g * 64 + ch] = hi;
            if (o1h) o1h[g * 64 + ch] = hi;
        }
    } else {
        const int t = px0 >> 13, b = (px0 >> 10) & 7;
        const size_t obase = (size_t)(b * TT + t) * 65536;
        for (int j = tid; j < 8192; j += 256) {
            const int xx = j & 31, yy = (j >> 5) & 3, ch = j >> 7;
            const float v = sigf(Dt[(yy * 32 + xx) * 68 + ch] + bias[ch]);
            dec[obase + (size_t)((ch >> 3) * 32 + y0 + yy) * 256 + (ch & 7) * 32 + xx] = v;
        }
    }
}

// ---------------- gate 1 ----------------
__global__ void gate1_k(const float* __restrict__ xhm, float* __restrict__ c,
                        float* __restrict__ m, bf* __restrict__ memh,
                        bf* __restrict__ mh)
{
    const int idx = blockIdx.x * 256 + threadIdx.x;
    const int px = idx >> 6, ch = idx & 63;
    const float* v = xhm + (size_t)px * 896;
    const float it  = sigf(v[ch]        + v[448 + ch]);
    const float ft  = sigf(v[64 + ch]   + v[512 + ch]);
    const float gt  = tanhf(v[128 + ch] + v[576 + ch]);
    const float cn  = ft * c[idx] + it * gt;
    const float itp = sigf(v[192 + ch]  + v[704 + ch]);
    const float ftp = sigf(v[256 + ch]  + v[768 + ch]);
    const float gtp = tanhf(v[320 + ch] + v[832 + ch]);
    const float mn  = ftp * m[idx] + itp * gtp;
    c[idx] = cn; m[idx] = mn;
    const bf chi = __float2bfloat16(cn);
    const bf mhi = __float2bfloat16(mn);
    memh[(size_t)px * 128 + ch]      = chi;
    memh[(size_t)px * 128 + 64 + ch] = mhi;
    mh[idx] = mhi;
}

// ---------------- patch (space-to-depth, NHWC, bf16) ----------------
__global__ void patch_k(const float* __restrict__ x, bf* __restrict__ xh)
{
    const int idx = blockIdx.x * 256 + threadIdx.x;
    const int ch = idx & 63, yx = (idx >> 6) & 1023;
    const int b = (idx >> 16) & 7, t = idx >> 19;
    xh[idx] = __float2bfloat16(
        x[(size_t)(b * INLEN + t) * 65536 +
          (size_t)((ch >> 3) * 32 + (yx >> 5)) * 256 + (ch & 7) * 32 + (yx & 31)]);
}

// ---------------- fused zero (one launch) ----------------
__global__ void zero_all(float4* hh, float4* mh, float4* c, float4* m)
{
    const int i = blockIdx.x * 256 + threadIdx.x;
    const float4 z = make_float4(0.f, 0.f, 0.f, 0.f);
    if (i < 262144)       hh[i] = z;                 // 4*LS bf16
    else if (i < 327680)  mh[i - 262144] = z;        // LS bf16
    else if (i < 851968)  c[i - 327680] = z;         // 4*LS f32
    else                  m[i - 851968] = z;         // LS f32
}

// ---------------- weight prep (bf16) ----------------
__global__ void prepW1_k(const float* __restrict__ Wx, const float* __restrict__ Wh,
                         const float* __restrict__ Wm, bf* __restrict__ dst)
{
    const int idx = blockIdx.x * 256 + threadIdx.x;   // 4*14*18*2048
    const int kk = idx & 31, row = (idx >> 5) & 63;
    const int c = (idx >> 11) % 18, r2 = (idx >> 11) / 18;
    const int mt = r2 % 14, l = r2 / 14;
    const int co = mt * 64 + row, tap = c >> 1, ci = ((c & 1) << 5) + kk;
    float v;
    if (co < 448)      v = Wx[((size_t)(l * 448 + co) * 64 + ci) * 9 + tap];
    else if (co < 704) v = Wh[((size_t)(l * 256 + co - 448) * 64 + ci) * 9 + tap];
    else               v = Wm[((size_t)(l * 192 + co - 704) * 64 + ci) * 9 + tap];
    dst[((size_t)(l * 14 + mt) * 18 + c) * 2048 + row * 32 + kk] = __float2bfloat16(v);
}

__global__ void prepW2_k(const float* __restrict__ Wo, const float* __restrict__ Wl,
                         bf* __restrict__ dst)
{
    const int idx = blockIdx.x * 256 + threadIdx.x;   // 4*36*4096
    const int kk = idx & 31, row = (idx >> 5) & 127;
    const int c = (idx >> 12) % 36, l = (idx >> 12) / 36;
    const int tap = c >> 2, ci = ((c & 3) << 5) + kk;
    float v = 0.f;
    if (row < 64)      v = Wo[((size_t)(l * 64 + row) * 128 + ci) * 9 + tap];
    else if (tap == 4) v = Wl[(size_t)(l * 64 + row - 64) * 128 + ci];
    dst[((size_t)(l * 36 + c)) * 4096 + row * 32 + kk] = __float2bfloat16(v);
}

__global__ void prep_rest_k(const float* __restrict__ Wd,
                            const float* __restrict__ bx, const float* __restrict__ bh,
                            const float* __restrict__ bm, const float* __restrict__ bo,
                            const float* __restrict__ bl,
                            bf* __restrict__ dWd,
                            float* __restrict__ b1, float* __restrict__ b2)
{
    const int idx = blockIdx.x * 256 + threadIdx.x;
    if (idx < 36864) {          // Wd: 18c x 64row x 32kk
        const int kk = idx & 31, row = (idx >> 5) & 63, c = idx >> 11;
        const int tap = c >> 1, ci = ((c & 1) << 5) + kk;
        dWd[(size_t)c * 2048 + row * 32 + kk] =
            __float2bfloat16(Wd[((size_t)row * 64 + ci) * 9 + tap]);
    } else if (idx < 40448) {   // b1: 4*896
        const int j = idx - 36864;
        const int l = j / 896, q = j % 896;
        b1[j] = q < 448 ? bx[l * 448 + q]
              : q < 704 ? bh[l * 256 + q - 448]
                        : bm[l * 192 + q - 704];
    } else if (idx < 40960) {   // b2: 4*128
        const int j = idx - 40448;
        const int l = j / 128, q = j % 128;
        b2[j] = q < 64 ? bo[l * 64 + q] : bl[l * 64 + q - 64];
    }
}

// =====================================================================
extern "C" void kernel_launch(void* const* d_in, const int* in_sizes, int n_in,
                              void* d_out, int out_size)
{
    const float* x  = (const float*)d_in[0];
    const float* Wx = (const float*)d_in[3];
    const float* bx = (const float*)d_in[4];
    const float* Wh = (const float*)d_in[5];
    const float* bh = (const float*)d_in[6];
    const float* Wm = (const float*)d_in[7];
    const float* bm = (const float*)d_in[8];
    const float* Wo = (const float*)d_in[9];
    const float* bo = (const float*)d_in[10];
    const float* Wl = (const float*)d_in[11];
    const float* bl = (const float*)d_in[12];
    const float* Wd = (const float*)d_in[13];
    const float* bd = (const float*)d_in[14];
    float* out = (float*)d_out;

    bf *xh, *hh, *mh, *memh, *oth, *W1, *W2, *W3;
    float *c, *m, *xhm, *b1, *b2;
    cudaGetSymbolAddress((void**)&xh,   g_xh);
    cudaGetSymbolAddress((void**)&hh,   g_hh);
    cudaGetSymbolAddress((void**)&mh,   g_mh);
    cudaGetSymbolAddress((void**)&memh, g_memh);
    cudaGetSymbolAddress((void**)&oth,  g_oth);
    cudaGetSymbolAddress((void**)&c,    g_c);
    cudaGetSymbolAddress((void**)&m,    g_m);
    cudaGetSymbolAddress((void**)&xhm,  g_xhm);
    cudaGetSymbolAddress((void**)&W1,   g_W1);
    cudaGetSymbolAddress((void**)&W2,   g_W2);
    cudaGetSymbolAddress((void**)&W3,   g_W3);
    cudaGetSymbolAddress((void**)&b1,   g_b1);
    cudaGetSymbolAddress((void**)&b2,   g_b2);

    // smem: APLANE + 2*WPLANE
    const int SM1 = 204 * 144 + 2 * 5120;    // 39616
    const int SM2 = 136 * 272 + 2 * 10240;   // 57472
    cudaFuncSetAttribute(gemm_k<64, 64, 128, 0>,
                         cudaFuncAttributeMaxDynamicSharedMemorySize, SM1);
    cudaFuncSetAttribute(gemm_k<128, 128, 64, 1>,
                         cudaFuncAttributeMaxDynamicSharedMemorySize, SM2);
    cudaFuncSetAttribute(gemm_k<64, 64, 128, 2>,
                         cudaFuncAttributeMaxDynamicSharedMemorySize, SM1);

    // launches 0-4 (so ncu -s 5 profiles the first gemm1)
    zero_all<<<3840, 256>>>((float4*)hh, (float4*)mh, (float4*)c, (float4*)m);
    patch_k<<<20480, 256>>>(x, xh);
    prepW1_k<<<8064, 256>>>(Wx, Wh, Wm, W1);
    prepW2_k<<<2304, 256>>>(Wo, Wl, W2);
    prep_rest_k<<<160, 256>>>(Wd, bx, bh, bm, bo, bl, W3, b1, b2);

    for (int t = 0; t < TT; t++) {
        const bf* curh = (t < INLEN) ? (xh + (size_t)t * LS) : (oth + (size_t)(t - 1) * LS);
        for (int l = 0; l < 4; l++) {
            const bf* inh = (l == 0) ? curh : (hh + (size_t)(l - 1) * LS);
            gemm_k<64, 64, 128, 0><<<dim3(64, 14), 256, SM1>>>(
                inh, hh + (size_t)l * LS, mh,
                W1 + (size_t)l * 14 * 18 * 2048, b1 + l * 896, xhm,
                nullptr, nullptr, nullptr);
            gate1_k<<<2048, 256>>>(xhm, c + (size_t)l * LS, m, memh, mh);
            gemm_k<128, 128, 64, 1><<<dim3(128, 1), 256, SM2>>>(
                memh, nullptr, nullptr,
                W2 + (size_t)l * 36 * 4096, b2 + l * 128, xhm,
                hh + (size_t)l * LS,
                (l == 3) ? (oth + (size_t)t * LS) : nullptr, nullptr);
        }
    }

    gemm_k<64, 64, 128, 2><<<dim3(1216, 1), 256, SM1>>>(
        oth, nullptr, nullptr, W3, bd, nullptr, nullptr, nullptr, out);
}